// round 2
// baseline (speedup 1.0000x reference)
#include <cuda_runtime.h>
#include <cuda_bf16.h>
#include <math.h>

// ---------------------------------------------------------------------------
// Problem constants
// ---------------------------------------------------------------------------
#define B_   1024
#define D_   1024
#define H4   4096
#define BAR_ 32
#define EPS_ 1e-5f

// ---------------------------------------------------------------------------
// Scratch (device globals: no allocations allowed)
// ---------------------------------------------------------------------------
__device__ float g_zn   [B_ * D_];
__device__ float g_h0   [B_ * D_];
__device__ float g_c0   [B_ * D_];
__device__ float g_h1   [B_ * D_];
__device__ float g_c1   [B_ * D_];
__device__ float g_x0p  [B_ * H4];          // x0_proj (+ both layer-0 biases)
__device__ float g_gates[B_ * H4];
__device__ float g_feats[(size_t)B_ * BAR_ * D_];   // (B, 32, H)
__device__ float g_scale[D_];
__device__ float g_shift[D_];
__device__ float g_b0   [H4];               // b_ih0 + b_hh0
__device__ float g_b1   [H4];               // b_ih1 + b_hh1

// ---------------------------------------------------------------------------
// BatchNorm statistics: one block handles 32 columns, blockDim = (32, 8)
// ---------------------------------------------------------------------------
__global__ void bn_stats_kernel(const float* __restrict__ z,
                                const float* __restrict__ gamma,
                                const float* __restrict__ beta) {
    __shared__ float ssum[8][32];
    __shared__ float ssq [8][32];
    int col = blockIdx.x * 32 + threadIdx.x;
    float s = 0.f, q = 0.f;
    for (int r = threadIdx.y; r < B_; r += 8) {
        float v = z[(size_t)r * D_ + col];
        s += v;
        q += v * v;
    }
    ssum[threadIdx.y][threadIdx.x] = s;
    ssq [threadIdx.y][threadIdx.x] = q;
    __syncthreads();
    if (threadIdx.y == 0) {
#pragma unroll
        for (int y = 1; y < 8; y++) {
            s += ssum[y][threadIdx.x];
            q += ssq [y][threadIdx.x];
        }
        float mean = s * (1.f / (float)B_);
        float var  = q * (1.f / (float)B_) - mean * mean;
        float sc   = gamma[col] * rsqrtf(var + EPS_);
        g_scale[col] = sc;
        g_shift[col] = beta[col] - mean * sc;
    }
}

// Apply BN and initialize zn, h0, c0, h1, c1 (all equal zn)
__global__ void bn_apply_init_kernel(const float* __restrict__ z) {
    int idx = blockIdx.x * blockDim.x + threadIdx.x;
    int col = idx & (D_ - 1);
    float v = z[idx] * g_scale[col] + g_shift[col];
    g_zn[idx] = v;
    g_h0[idx] = v; g_c0[idx] = v;
    g_h1[idx] = v; g_c1[idx] = v;
}

// Precompute combined biases
__global__ void bias_sum_kernel(const float* __restrict__ b_ih0,
                                const float* __restrict__ b_hh0,
                                const float* __restrict__ b_ih1,
                                const float* __restrict__ b_hh1) {
    int i = blockIdx.x * blockDim.x + threadIdx.x;
    if (i < H4) {
        g_b0[i] = b_ih0[i] + b_hh0[i];
        g_b1[i] = b_ih1[i] + b_hh1[i];
    }
}

// ---------------------------------------------------------------------------
// Generic fp32 GEMM:  C[M,N] = (Cinit? Cinit : 0) + (bias? bias : 0)
//                              + A1[M,K1] @ B1[N,K1]^T  (+ A2[M,K2] @ B2[N,K2]^T)
// Both A and B are K-major (row stride == their K). Tile 128x128x16,
// 256 threads, 8x8 per thread. All dims assumed multiples of the tile.
// ---------------------------------------------------------------------------
#define BM 128
#define BN 128
#define BK 16
#define TM 8
#define TN 8

__global__ __launch_bounds__(256, 2)
void gemm_kernel(const float* __restrict__ A1, const float* __restrict__ B1, int K1,
                 const float* __restrict__ A2, const float* __restrict__ B2, int K2,
                 const float* __restrict__ Cinit, const float* __restrict__ bias,
                 float* __restrict__ C, int M, int N) {
    __shared__ float As[BK][BM + 4];
    __shared__ float Bs[BK][BN + 4];

    const int tid = threadIdx.x;
    const int tx = tid & 15;       // 0..15 -> N direction
    const int ty = tid >> 4;       // 0..15 -> M direction
    const int row0 = blockIdx.y * BM;
    const int col0 = blockIdx.x * BN;

    const int lr = tid >> 2;       // 0..63 loader row
    const int lc = tid & 3;        // 0..3  loader float4 column

    float acc[TM][TN];
#pragma unroll
    for (int i = 0; i < TM; i++)
#pragma unroll
        for (int j = 0; j < TN; j++) acc[i][j] = 0.f;

    const int Ktot = K1 + K2;
    for (int k0 = 0; k0 < Ktot; k0 += BK) {
        const float* A; const float* Bm; int kk, ldk;
        if (k0 < K1) { A = A1; Bm = B1; kk = k0;      ldk = K1; }
        else         { A = A2; Bm = B2; kk = k0 - K1; ldk = K2; }

#pragma unroll
        for (int s = 0; s < 2; s++) {
            int r = lr + s * 64;
            float4 va = *(const float4*)(A  + (size_t)(row0 + r) * ldk + kk + lc * 4);
            As[lc * 4 + 0][r] = va.x;
            As[lc * 4 + 1][r] = va.y;
            As[lc * 4 + 2][r] = va.z;
            As[lc * 4 + 3][r] = va.w;
            float4 vb = *(const float4*)(Bm + (size_t)(col0 + r) * ldk + kk + lc * 4);
            Bs[lc * 4 + 0][r] = vb.x;
            Bs[lc * 4 + 1][r] = vb.y;
            Bs[lc * 4 + 2][r] = vb.z;
            Bs[lc * 4 + 3][r] = vb.w;
        }
        __syncthreads();

#pragma unroll
        for (int k = 0; k < BK; k++) {
            float a[TM], b[TN];
            float4 a0 = *(const float4*)&As[k][ty * TM];
            float4 a1 = *(const float4*)&As[k][ty * TM + 4];
            a[0]=a0.x; a[1]=a0.y; a[2]=a0.z; a[3]=a0.w;
            a[4]=a1.x; a[5]=a1.y; a[6]=a1.z; a[7]=a1.w;
            float4 b0 = *(const float4*)&Bs[k][tx * TN];
            float4 b1 = *(const float4*)&Bs[k][tx * TN + 4];
            b[0]=b0.x; b[1]=b0.y; b[2]=b0.z; b[3]=b0.w;
            b[4]=b1.x; b[5]=b1.y; b[6]=b1.z; b[7]=b1.w;
#pragma unroll
            for (int i = 0; i < TM; i++)
#pragma unroll
                for (int j = 0; j < TN; j++)
                    acc[i][j] = fmaf(a[i], b[j], acc[i][j]);
        }
        __syncthreads();
    }

    // Epilogue
#pragma unroll
    for (int i = 0; i < TM; i++) {
        int m = row0 + ty * TM + i;
        size_t base = (size_t)m * N + col0 + tx * TN;
#pragma unroll
        for (int jj = 0; jj < TN; jj += 4) {
            float4 v;
            v.x = acc[i][jj + 0];
            v.y = acc[i][jj + 1];
            v.z = acc[i][jj + 2];
            v.w = acc[i][jj + 3];
            int n = col0 + tx * TN + jj;
            if (bias) {
                v.x += bias[n + 0]; v.y += bias[n + 1];
                v.z += bias[n + 2]; v.w += bias[n + 3];
            }
            if (Cinit) {
                float4 ci = *(const float4*)(Cinit + base + jj);
                v.x += ci.x; v.y += ci.y; v.z += ci.z; v.w += ci.w;
            }
            *(float4*)(C + base + jj) = v;
        }
    }
}

// ---------------------------------------------------------------------------
// LSTM cell elementwise: gates (B,4H) order (i,f,g,o); in-place h,c update.
// Optionally scatter h_new into feats at step t.
// ---------------------------------------------------------------------------
__device__ __forceinline__ float sigmoidf_(float x) {
    return 1.f / (1.f + expf(-x));
}

__global__ void lstm_cell_kernel(const float* __restrict__ gates,
                                 float* __restrict__ h, float* __restrict__ c,
                                 float* __restrict__ feats, int t) {
    int idx = blockIdx.x * blockDim.x + threadIdx.x;   // 0 .. B*H-1
    int b  = idx >> 10;
    int hh = idx & (D_ - 1);
    const float* gr = gates + (size_t)b * H4;
    float gi = sigmoidf_(gr[hh]);
    float gf = sigmoidf_(gr[D_ + hh]);
    float gg = tanhf    (gr[2 * D_ + hh]);
    float go = sigmoidf_(gr[3 * D_ + hh]);
    float cn = gf * c[idx] + gi * gg;
    float hn = go * tanhf(cn);
    c[idx] = cn;
    h[idx] = hn;
    if (feats) feats[((size_t)b * BAR_ + t) * D_ + hh] = hn;
}

// ---------------------------------------------------------------------------
// Launch
// ---------------------------------------------------------------------------
extern "C" void kernel_launch(void* const* d_in, const int* in_sizes, int n_in,
                              void* d_out, int out_size) {
    const float* z       = (const float*)d_in[0];
    const float* gamma   = (const float*)d_in[1];
    const float* beta    = (const float*)d_in[2];
    const float* W_ih0   = (const float*)d_in[3];
    const float* W_hh0   = (const float*)d_in[4];
    const float* b_ih0   = (const float*)d_in[5];
    const float* b_hh0   = (const float*)d_in[6];
    const float* W_ih1   = (const float*)d_in[7];
    const float* W_hh1   = (const float*)d_in[8];
    const float* b_ih1   = (const float*)d_in[9];
    const float* b_hh1   = (const float*)d_in[10];
    const float* W_lin   = (const float*)d_in[11];
    const float* b_lin   = (const float*)d_in[12];
    float* out = (float*)d_out;

    float *zn, *h0, *c0, *h1, *c1, *x0p, *gates, *feats, *b0, *b1;
    cudaGetSymbolAddress((void**)&zn,    g_zn);
    cudaGetSymbolAddress((void**)&h0,    g_h0);
    cudaGetSymbolAddress((void**)&c0,    g_c0);
    cudaGetSymbolAddress((void**)&h1,    g_h1);
    cudaGetSymbolAddress((void**)&c1,    g_c1);
    cudaGetSymbolAddress((void**)&x0p,   g_x0p);
    cudaGetSymbolAddress((void**)&gates, g_gates);
    cudaGetSymbolAddress((void**)&feats, g_feats);
    cudaGetSymbolAddress((void**)&b0,    g_b0);
    cudaGetSymbolAddress((void**)&b1,    g_b1);

    // 1. BatchNorm + state init
    bn_stats_kernel<<<D_ / 32, dim3(32, 8)>>>(z, gamma, beta);
    bn_apply_init_kernel<<<(B_ * D_) / 512, 512>>>(z);
    bias_sum_kernel<<<H4 / 256, 256>>>(b_ih0, b_hh0, b_ih1, b_hh1);

    // 2. x0_proj = zn @ W_ih0^T + (b_ih0 + b_hh0)
    gemm_kernel<<<dim3(H4 / BN, B_ / BM), 256>>>(
        zn, W_ih0, D_, nullptr, nullptr, 0, nullptr, b0, x0p, B_, H4);

    // 3. 32 recurrent steps
    for (int t = 0; t < BAR_; t++) {
        // layer 0: gates = x0_proj + h0 @ W_hh0^T
        gemm_kernel<<<dim3(H4 / BN, B_ / BM), 256>>>(
            h0, W_hh0, D_, nullptr, nullptr, 0, x0p, nullptr, gates, B_, H4);
        lstm_cell_kernel<<<(B_ * D_) / 512, 512>>>(gates, h0, c0, nullptr, 0);

        // layer 1: gates = h0 @ W_ih1^T + h1 @ W_hh1^T + (b_ih1 + b_hh1)
        gemm_kernel<<<dim3(H4 / BN, B_ / BM), 256>>>(
            h0, W_ih1, D_, h1, W_hh1, D_, nullptr, b1, gates, B_, H4);
        lstm_cell_kernel<<<(B_ * D_) / 512, 512>>>(gates, h1, c1, feats, t);
    }

    // 4. out = feats(B*32, H) @ W_lin^T + b_lin
    gemm_kernel<<<dim3(D_ / BN, (B_ * BAR_) / BM), 256>>>(
        feats, W_lin, D_, nullptr, nullptr, 0, nullptr, b_lin, out,
        B_ * BAR_, D_);
}

// round 5
// speedup vs baseline: 3.6165x; 3.6165x over previous
#include <cuda_runtime.h>
#include <cuda_bf16.h>
#include <math.h>
#include <cstdint>

// ---------------------------------------------------------------------------
// Problem constants
// ---------------------------------------------------------------------------
#define B_   1024
#define D_   1024
#define H4   4096
#define BAR_ 32
#define EPS_ 1e-5f

#define SMEM_SWIZZLE_128B(byte_offset) \
    ((byte_offset) ^ (((byte_offset) >> 3) & 0x70))

__device__ __forceinline__ uint32_t smem_to_u32(const void* smem_ptr) {
    uint32_t addr;
    asm("{ .reg .u64 tmp; cvta.to.shared.u64 tmp, %1; cvt.u32.u64 %0, tmp; }"
        : "=r"(addr) : "l"(smem_ptr));
    return addr;
}

__device__ __forceinline__ uint32_t lds32(uint32_t addr) {
    uint32_t v;
    asm volatile("ld.shared.b32 %0, [%1];" : "=r"(v) : "r"(addr));
    return v;
}

__device__ __forceinline__ float to_tf32(float x) {
    float r;
    asm("cvt.rna.tf32.f32 %0, %1;" : "=f"(r) : "f"(x));
    return r;
}

__device__ __forceinline__ void mma_tf32(float& d0, float& d1, float& d2, float& d3,
                                         uint32_t a0, uint32_t a1, uint32_t a2, uint32_t a3,
                                         uint32_t b0, uint32_t b1) {
    asm volatile(
        "mma.sync.aligned.m16n8k8.row.col.f32.tf32.tf32.f32 "
        "{%0,%1,%2,%3}, {%4,%5,%6,%7}, {%8,%9}, {%0,%1,%2,%3};"
        : "+f"(d0), "+f"(d1), "+f"(d2), "+f"(d3)
        : "r"(a0), "r"(a1), "r"(a2), "r"(a3), "r"(b0), "r"(b1));
}

__device__ __forceinline__ void cp_async16(uint32_t dst, const void* src) {
    asm volatile("cp.async.cg.shared.global [%0], [%1], 16;"
                 :: "r"(dst), "l"(src) : "memory");
}
#define CP_COMMIT() asm volatile("cp.async.commit_group;" ::: "memory")
#define CP_WAIT(N)  asm volatile("cp.async.wait_group %0;" :: "n"(N) : "memory")

// ---------------------------------------------------------------------------
// Scratch (device globals: no allocations allowed)
// ---------------------------------------------------------------------------
__device__ float g_zn   [B_ * D_];
__device__ float g_h0   [B_ * D_];
__device__ float g_c0   [B_ * D_];
__device__ float g_h1   [B_ * D_];
__device__ float g_c1   [B_ * D_];
__device__ float g_x0p  [B_ * H4];
__device__ float g_gates[B_ * H4];
__device__ float g_feats[(size_t)B_ * BAR_ * D_];
__device__ float g_scale[D_];
__device__ float g_shift[D_];
__device__ float g_b0   [H4];
__device__ float g_b1   [H4];
__device__ float g_wih0 [H4 * D_];
__device__ float g_whh0 [H4 * D_];
__device__ float g_wih1 [H4 * D_];
__device__ float g_whh1 [H4 * D_];
__device__ float g_wlin [D_ * D_];

// ---------------------------------------------------------------------------
// Small prep kernels
// ---------------------------------------------------------------------------
__global__ void bn_stats_kernel(const float* __restrict__ z,
                                const float* __restrict__ gamma,
                                const float* __restrict__ beta) {
    __shared__ float ssum[8][32];
    __shared__ float ssq [8][32];
    int col = blockIdx.x * 32 + threadIdx.x;
    float s = 0.f, q = 0.f;
    for (int r = threadIdx.y; r < B_; r += 8) {
        float v = z[(size_t)r * D_ + col];
        s += v; q += v * v;
    }
    ssum[threadIdx.y][threadIdx.x] = s;
    ssq [threadIdx.y][threadIdx.x] = q;
    __syncthreads();
    if (threadIdx.y == 0) {
#pragma unroll
        for (int y = 1; y < 8; y++) { s += ssum[y][threadIdx.x]; q += ssq[y][threadIdx.x]; }
        float mean = s * (1.f / (float)B_);
        float var  = q * (1.f / (float)B_) - mean * mean;
        float sc   = gamma[col] * rsqrtf(var + EPS_);
        g_scale[col] = sc;
        g_shift[col] = beta[col] - mean * sc;
    }
}

__global__ void bn_apply_init_kernel(const float* __restrict__ z) {
    int idx = blockIdx.x * blockDim.x + threadIdx.x;
    int col = idx & (D_ - 1);
    float v = to_tf32(z[idx] * g_scale[col] + g_shift[col]);
    g_zn[idx] = v;
    g_h0[idx] = v; g_c0[idx] = v;
    g_h1[idx] = v; g_c1[idx] = v;
}

__global__ void bias_sum_kernel(const float* __restrict__ b_ih0,
                                const float* __restrict__ b_hh0,
                                const float* __restrict__ b_ih1,
                                const float* __restrict__ b_hh1) {
    int i = blockIdx.x * blockDim.x + threadIdx.x;
    if (i < H4) {
        g_b0[i] = b_ih0[i] + b_hh0[i];
        g_b1[i] = b_ih1[i] + b_hh1[i];
    }
}

__global__ void round_tf32_kernel(const float* __restrict__ src,
                                  float* __restrict__ dst, int n4) {
    int i = blockIdx.x * blockDim.x + threadIdx.x;
    if (i < n4) {
        float4 v = ((const float4*)src)[i];
        v.x = to_tf32(v.x); v.y = to_tf32(v.y);
        v.z = to_tf32(v.z); v.w = to_tf32(v.w);
        ((float4*)dst)[i] = v;
    }
}

// ---------------------------------------------------------------------------
// tf32 mma.sync GEMM:
//   C[M,Nfull] = (Cinit?) + (bias?) + A1[M,K1]@B1[Nfull,K1]^T (+ A2@B2^T)
// Tile 128x128x32, 256 threads (8 warps, 2x4), warp tile 64x32.
// cp.async double-buffered smem, SW128 XOR swizzle (conflict-free frag LDS).
// smem layout: A bufs @ 0 / 16K, B bufs @ 32K / 48K  (relative to aligned base)
// ---------------------------------------------------------------------------
#define TM_ 128
#define TN_ 128
#define TK_ 32

#define DYN_BYTES (65536u + 1024u)

__global__ __launch_bounds__(256, 2)
void gemm_mma_kernel(const float* __restrict__ A1, const float* __restrict__ B1, int K1,
                     const float* __restrict__ A2, const float* __restrict__ B2, int K2,
                     const float* __restrict__ Cinit, const float* __restrict__ bias,
                     float* __restrict__ C, int Nfull) {
    extern __shared__ char dyn_smem[];
    uint32_t raw  = smem_to_u32(dyn_smem);
    uint32_t base = (raw + 1023u) & ~1023u;

    const int tid  = threadIdx.x;
    const int wid  = tid >> 5;
    const int lane = tid & 31;
    const int lg   = lane >> 2;        // group id 0..7
    const int lt   = lane & 3;         // thread-in-group 0..3
    const int wm   = wid >> 2;         // 0..1  (M direction)
    const int wn   = wid & 3;          // 0..3  (N direction)
    const int row0 = blockIdx.y * TM_;
    const int col0 = blockIdx.x * TN_;
    const int m0   = wm * 64;
    const int n0   = wn * 32;

    // loader coords: 1024 float4 per operand tile, 4 per thread
    const int lr0 = tid >> 3;          // base row (stride 32 over i)
    const int lc  = tid & 7;           // float4 column 0..7

    float acc[4][4][4];
#pragma unroll
    for (int mi = 0; mi < 4; mi++)
#pragma unroll
        for (int ni = 0; ni < 4; ni++)
#pragma unroll
            for (int r = 0; r < 4; r++) acc[mi][ni][r] = 0.f;

    const int nk = (K1 + K2) / TK_;

    auto load_chunk = [&](int kc, int bsel) {
        const float* Ag; const float* Bg; int kk, ldk;
        int k0 = kc * TK_;
        if (k0 < K1) { Ag = A1; Bg = B1; kk = k0;      ldk = K1; }
        else         { Ag = A2; Bg = B2; kk = k0 - K1; ldk = K2; }
        uint32_t sa = base + ((uint32_t)bsel << 14);             // 0 / 16K
        uint32_t sb = base + 32768u + ((uint32_t)bsel << 14);    // 32K / 48K
#pragma unroll
        for (int i = 0; i < 4; i++) {
            int r = lr0 + i * 32;
            cp_async16(sa + SMEM_SWIZZLE_128B(r * 128 + lc * 16),
                       Ag + (size_t)(row0 + r) * ldk + kk + lc * 4);
            cp_async16(sb + SMEM_SWIZZLE_128B(r * 128 + lc * 16),
                       Bg + (size_t)(col0 + r) * ldk + kk + lc * 4);
        }
        CP_COMMIT();
    };

    load_chunk(0, 0);

    for (int k = 0; k < nk; k++) {
        int bsel = k & 1;
        if (k + 1 < nk) {
            load_chunk(k + 1, bsel ^ 1);
            CP_WAIT(1);
        } else {
            CP_WAIT(0);
        }
        __syncthreads();

        uint32_t sa = base + ((uint32_t)bsel << 14);
        uint32_t sb = base + 32768u + ((uint32_t)bsel << 14);
        // swizzled column offset for this thread's k-fragment elements:
        // addr(r, k) = r*128 + ((k*4) ^ ((r&7)<<4)); our rows have (r&7)==lg
#pragma unroll
        for (int ks = 0; ks < 4; ks++) {
            int kbase = ks * 8 + lt;        // k index for a0/b0 (a2/b1: +4)
            uint32_t koff  = (uint32_t)(kbase * 4) ^ ((uint32_t)lg << 4);
            uint32_t koff4 = (uint32_t)((kbase + 4) * 4) ^ ((uint32_t)lg << 4);

            uint32_t af[4][4];
#pragma unroll
            for (int mi = 0; mi < 4; mi++) {
                int r = m0 + mi * 16 + lg;
                uint32_t rb = sa + (uint32_t)(r * 128);
                af[mi][0] = lds32(rb + koff);
                af[mi][1] = lds32(rb + 8 * 128 + koff);
                af[mi][2] = lds32(rb + koff4);
                af[mi][3] = lds32(rb + 8 * 128 + koff4);
            }
            uint32_t bf[4][2];
#pragma unroll
            for (int ni = 0; ni < 4; ni++) {
                int n = n0 + ni * 8 + lg;
                uint32_t nb = sb + (uint32_t)(n * 128);
                bf[ni][0] = lds32(nb + koff);
                bf[ni][1] = lds32(nb + koff4);
            }
#pragma unroll
            for (int mi = 0; mi < 4; mi++)
#pragma unroll
                for (int ni = 0; ni < 4; ni++)
                    mma_tf32(acc[mi][ni][0], acc[mi][ni][1],
                             acc[mi][ni][2], acc[mi][ni][3],
                             af[mi][0], af[mi][1], af[mi][2], af[mi][3],
                             bf[ni][0], bf[ni][1]);
        }
        __syncthreads();
    }

    // ---- Epilogue: direct float2 stores (32B per quad-row segment) ----
#pragma unroll
    for (int mi = 0; mi < 4; mi++) {
        int gr0 = row0 + m0 + mi * 16 + lg;
#pragma unroll
        for (int ni = 0; ni < 4; ni++) {
            int gc = col0 + n0 + ni * 8 + lt * 2;
            float bx = 0.f, by = 0.f;
            if (bias) { bx = bias[gc]; by = bias[gc + 1]; }
            size_t g0 = (size_t)gr0 * Nfull + gc;
            size_t g1 = g0 + (size_t)8 * Nfull;
            float2 v0 = make_float2(acc[mi][ni][0] + bx, acc[mi][ni][1] + by);
            float2 v1 = make_float2(acc[mi][ni][2] + bx, acc[mi][ni][3] + by);
            if (Cinit) {
                float2 c0 = *(const float2*)(Cinit + g0);
                float2 c1 = *(const float2*)(Cinit + g1);
                v0.x += c0.x; v0.y += c0.y;
                v1.x += c1.x; v1.y += c1.y;
            }
            *(float2*)(C + g0) = v0;
            *(float2*)(C + g1) = v1;
        }
    }
}

// ---------------------------------------------------------------------------
// LSTM cell elementwise (h rounded to tf32 for the next GEMM)
// ---------------------------------------------------------------------------
__device__ __forceinline__ float sigmoidf_(float x) {
    return 1.f / (1.f + expf(-x));
}

__global__ void lstm_cell_kernel(const float* __restrict__ gates,
                                 float* __restrict__ h, float* __restrict__ c,
                                 float* __restrict__ feats, int t) {
    int idx = blockIdx.x * blockDim.x + threadIdx.x;
    int b  = idx >> 10;
    int hh = idx & (D_ - 1);
    const float* gr = gates + (size_t)b * H4;
    float gi = sigmoidf_(gr[hh]);
    float gf = sigmoidf_(gr[D_ + hh]);
    float gg = tanhf    (gr[2 * D_ + hh]);
    float go = sigmoidf_(gr[3 * D_ + hh]);
    float cn = gf * c[idx] + gi * gg;
    float hn = to_tf32(go * tanhf(cn));
    c[idx] = cn;
    h[idx] = hn;
    if (feats) feats[((size_t)b * BAR_ + t) * D_ + hh] = hn;
}

// ---------------------------------------------------------------------------
// Launch
// ---------------------------------------------------------------------------
extern "C" void kernel_launch(void* const* d_in, const int* in_sizes, int n_in,
                              void* d_out, int out_size) {
    const float* z       = (const float*)d_in[0];
    const float* gamma   = (const float*)d_in[1];
    const float* beta    = (const float*)d_in[2];
    const float* W_ih0   = (const float*)d_in[3];
    const float* W_hh0   = (const float*)d_in[4];
    const float* b_ih0   = (const float*)d_in[5];
    const float* b_hh0   = (const float*)d_in[6];
    const float* W_ih1   = (const float*)d_in[7];
    const float* W_hh1   = (const float*)d_in[8];
    const float* b_ih1   = (const float*)d_in[9];
    const float* b_hh1   = (const float*)d_in[10];
    const float* W_lin   = (const float*)d_in[11];
    const float* b_lin   = (const float*)d_in[12];
    float* out = (float*)d_out;

    float *zn, *h0, *c0, *h1, *c1, *x0p, *gates, *feats, *b0, *b1;
    float *wih0, *whh0, *wih1, *whh1, *wlin;
    cudaGetSymbolAddress((void**)&zn,    g_zn);
    cudaGetSymbolAddress((void**)&h0,    g_h0);
    cudaGetSymbolAddress((void**)&c0,    g_c0);
    cudaGetSymbolAddress((void**)&h1,    g_h1);
    cudaGetSymbolAddress((void**)&c1,    g_c1);
    cudaGetSymbolAddress((void**)&x0p,   g_x0p);
    cudaGetSymbolAddress((void**)&gates, g_gates);
    cudaGetSymbolAddress((void**)&feats, g_feats);
    cudaGetSymbolAddress((void**)&b0,    g_b0);
    cudaGetSymbolAddress((void**)&b1,    g_b1);
    cudaGetSymbolAddress((void**)&wih0,  g_wih0);
    cudaGetSymbolAddress((void**)&whh0,  g_whh0);
    cudaGetSymbolAddress((void**)&wih1,  g_wih1);
    cudaGetSymbolAddress((void**)&whh1,  g_whh1);
    cudaGetSymbolAddress((void**)&wlin,  g_wlin);

    cudaFuncSetAttribute(gemm_mma_kernel,
                         cudaFuncAttributeMaxDynamicSharedMemorySize, DYN_BYTES);

    // 1. BatchNorm + state init + bias prep + weight tf32 rounding
    bn_stats_kernel<<<D_ / 32, dim3(32, 8)>>>(z, gamma, beta);
    bn_apply_init_kernel<<<(B_ * D_) / 512, 512>>>(z);
    bias_sum_kernel<<<H4 / 256, 256>>>(b_ih0, b_hh0, b_ih1, b_hh1);
    round_tf32_kernel<<<(H4 * D_ / 4) / 256, 256>>>(W_ih0, wih0, H4 * D_ / 4);
    round_tf32_kernel<<<(H4 * D_ / 4) / 256, 256>>>(W_hh0, whh0, H4 * D_ / 4);
    round_tf32_kernel<<<(H4 * D_ / 4) / 256, 256>>>(W_ih1, wih1, H4 * D_ / 4);
    round_tf32_kernel<<<(H4 * D_ / 4) / 256, 256>>>(W_hh1, whh1, H4 * D_ / 4);
    round_tf32_kernel<<<(D_ * D_ / 4) / 256, 256>>>(W_lin, wlin, D_ * D_ / 4);

    dim3 grid_layer(H4 / TN_, B_ / TM_);        // (32, 8) = 256 CTAs

    // 2. x0_proj = zn @ W_ih0^T + (b_ih0 + b_hh0)
    gemm_mma_kernel<<<grid_layer, 256, DYN_BYTES>>>(
        zn, wih0, D_, nullptr, nullptr, 0, nullptr, b0, x0p, H4);

    // 3. 32 recurrent steps
    for (int t = 0; t < BAR_; t++) {
        gemm_mma_kernel<<<grid_layer, 256, DYN_BYTES>>>(
            h0, whh0, D_, nullptr, nullptr, 0, x0p, nullptr, gates, H4);
        lstm_cell_kernel<<<(B_ * D_) / 512, 512>>>(gates, h0, c0, nullptr, 0);

        gemm_mma_kernel<<<grid_layer, 256, DYN_BYTES>>>(
            h0, wih1, D_, h1, whh1, D_, nullptr, b1, gates, H4);
        lstm_cell_kernel<<<(B_ * D_) / 512, 512>>>(gates, h1, c1, feats, t);
    }

    // 4. out = feats(B*32, H) @ W_lin^T + b_lin
    dim3 grid_head(D_ / TN_, (B_ * BAR_) / TM_);   // (8, 256)
    gemm_mma_kernel<<<grid_head, 256, DYN_BYTES>>>(
        feats, wlin, D_, nullptr, nullptr, 0, nullptr, b_lin, out, D_);
}

// round 9
// speedup vs baseline: 4.4553x; 1.2319x over previous
#include <cuda_runtime.h>
#include <cuda_fp16.h>
#include <math.h>
#include <cstdint>

// ---------------------------------------------------------------------------
// Problem constants
// ---------------------------------------------------------------------------
#define B_   1024
#define D_   1024
#define H4   4096
#define BAR_ 32
#define EPS_ 1e-5f

#define SMEM_SWIZZLE_128B(byte_offset) \
    ((byte_offset) ^ (((byte_offset) >> 3) & 0x70))

__device__ __forceinline__ uint32_t smem_to_u32(const void* smem_ptr) {
    uint32_t addr;
    asm("{ .reg .u64 tmp; cvta.to.shared.u64 tmp, %1; cvt.u32.u64 %0, tmp; }"
        : "=r"(addr) : "l"(smem_ptr));
    return addr;
}

__device__ __forceinline__ uint32_t lds32(uint32_t addr) {
    uint32_t v;
    asm volatile("ld.shared.b32 %0, [%1];" : "=r"(v) : "r"(addr));
    return v;
}

__device__ __forceinline__ void mma_fp16(float& d0, float& d1, float& d2, float& d3,
                                         uint32_t a0, uint32_t a1, uint32_t a2, uint32_t a3,
                                         uint32_t b0, uint32_t b1) {
    asm volatile(
        "mma.sync.aligned.m16n8k16.row.col.f32.f16.f16.f32 "
        "{%0,%1,%2,%3}, {%4,%5,%6,%7}, {%8,%9}, {%0,%1,%2,%3};"
        : "+f"(d0), "+f"(d1), "+f"(d2), "+f"(d3)
        : "r"(a0), "r"(a1), "r"(a2), "r"(a3), "r"(b0), "r"(b1));
}

__device__ __forceinline__ void cp_async16(uint32_t dst, const void* src) {
    asm volatile("cp.async.cg.shared.global [%0], [%1], 16;"
                 :: "r"(dst), "l"(src) : "memory");
}
#define CP_COMMIT() asm volatile("cp.async.commit_group;" ::: "memory")
#define CP_WAIT(N)  asm volatile("cp.async.wait_group %0;" :: "n"(N) : "memory")

__device__ __forceinline__ float sigmoidf_(float x) {
    return 1.f / (1.f + expf(-x));
}

// ---------------------------------------------------------------------------
// Scratch (device globals: no allocations allowed)
// h-states are PING-PONG buffered: the fused-cell kernel writes the next
// buffer while all CTAs read the current one (no cross-CTA race).
// ---------------------------------------------------------------------------
__device__ __half g_znh [B_ * D_];
__device__ __half g_h0a [B_ * D_];
__device__ __half g_h0b [B_ * D_];
__device__ __half g_h1a [B_ * D_];
__device__ __half g_h1b [B_ * D_];
__device__ float  g_c0  [B_ * D_];
__device__ float  g_c1  [B_ * D_];
__device__ float  g_x0p [B_ * H4];            // interleaved gate cols, fp32
__device__ __half g_feats[(size_t)B_ * BAR_ * D_];  // (B, 32, H) fp16
__device__ float  g_scale[D_];
__device__ float  g_shift[D_];
__device__ float  g_b0i [H4];                 // interleaved b_ih0+b_hh0
__device__ float  g_b1i [H4];                 // interleaved b_ih1+b_hh1
__device__ __half g_wih0[H4 * D_];            // gate-interleaved fp16 weights
__device__ __half g_whh0[H4 * D_];
__device__ __half g_wih1[H4 * D_];
__device__ __half g_whh1[H4 * D_];
__device__ __half g_wlin[D_ * D_];            // plain fp16

// ---------------------------------------------------------------------------
// Prep kernels
// ---------------------------------------------------------------------------
__global__ void bn_stats_kernel(const float* __restrict__ z,
                                const float* __restrict__ gamma,
                                const float* __restrict__ beta) {
    __shared__ float ssum[8][32];
    __shared__ float ssq [8][32];
    int col = blockIdx.x * 32 + threadIdx.x;
    float s = 0.f, q = 0.f;
    for (int r = threadIdx.y; r < B_; r += 8) {
        float v = z[(size_t)r * D_ + col];
        s += v; q += v * v;
    }
    ssum[threadIdx.y][threadIdx.x] = s;
    ssq [threadIdx.y][threadIdx.x] = q;
    __syncthreads();
    if (threadIdx.y == 0) {
#pragma unroll
        for (int y = 1; y < 8; y++) { s += ssum[y][threadIdx.x]; q += ssq[y][threadIdx.x]; }
        float mean = s * (1.f / (float)B_);
        float var  = q * (1.f / (float)B_) - mean * mean;
        float sc   = gamma[col] * rsqrtf(var + EPS_);
        g_scale[col] = sc;
        g_shift[col] = beta[col] - mean * sc;
    }
}

// zn -> fp16 A-operand + fp32 c-state inits (h inits are the fp16 zn)
__global__ void bn_apply_init_kernel(const float* __restrict__ z) {
    int idx = blockIdx.x * blockDim.x + threadIdx.x;
    int col = idx & (D_ - 1);
    float v = z[idx] * g_scale[col] + g_shift[col];
    __half vh = __float2half_rn(v);
    g_znh[idx] = vh;
    g_h0a[idx] = vh; g_h1a[idx] = vh;
    float vr = __half2float(vh);   // h/c start identical to what GEMM sees
    g_c0[idx] = vr;  g_c1[idx] = vr;
}

// interleaved bias: out[4h+g] = b_ih[g*D+h] + b_hh[g*D+h]
__global__ void bias_interleave_kernel(const float* __restrict__ b_ih0,
                                       const float* __restrict__ b_hh0,
                                       const float* __restrict__ b_ih1,
                                       const float* __restrict__ b_hh1) {
    int j = blockIdx.x * blockDim.x + threadIdx.x;
    if (j < H4) {
        int g = j & 3, h = j >> 2;
        g_b0i[j] = b_ih0[g * D_ + h] + b_hh0[g * D_ + h];
        g_b1i[j] = b_ih1[g * D_ + h] + b_hh1[g * D_ + h];
    }
}

// gate-interleave + fp16 convert: dst[(4*(r%D)+(r/D))*D + k] = fp16(src[r*D+k])
__global__ void weight_interleave_kernel(const float* __restrict__ src,
                                         __half* __restrict__ dst) {
    int j = blockIdx.x * blockDim.x + threadIdx.x;   // over H4*D_/4 float4s
    int nr = j >> 8;                                  // new row (k in float4s: 256)
    int k4 = j & 255;
    int r_old = (nr & 3) * D_ + (nr >> 2);
    float4 v = *(const float4*)(src + (size_t)r_old * D_ + k4 * 4);
    __half2* d = (__half2*)(dst + (size_t)nr * D_ + k4 * 4);
    d[0] = __floats2half2_rn(v.x, v.y);
    d[1] = __floats2half2_rn(v.z, v.w);
}

__global__ void weight_fp16_kernel(const float* __restrict__ src,
                                   __half* __restrict__ dst, int n4) {
    int i = blockIdx.x * blockDim.x + threadIdx.x;
    if (i < n4) {
        float4 v = ((const float4*)src)[i];
        __half2* d = (__half2*)(dst + (size_t)i * 4);
        d[0] = __floats2half2_rn(v.x, v.y);
        d[1] = __floats2half2_rn(v.z, v.w);
    }
}

// ---------------------------------------------------------------------------
// fp16 mma.sync GEMM, tile 128x128x64(fp16), 8 warps (2x4), warp tile 64x32.
// MODE 0: C[M,Nfull](fp32) = bias + Cinit + A1@B1^T (+A2@B2^T)
// MODE 1: fused LSTM cell epilogue (gate-interleaved columns, Nfull=4096):
//         gates = bias? + Cinit? + GEMM; update cstate in-place, write hout
//         (MUST be a different buffer than A1/A2!), optional feats at step t.
// smem: A bufs @ 0/16K, B bufs @ 32K/48K (relative to 1024-aligned base)
// ---------------------------------------------------------------------------
#define TK_ 64
#define DYN_BYTES (65536u + 1024u)

template<int MODE>
__global__ __launch_bounds__(256, 2)
void gemm_mma_kernel(const __half* __restrict__ A1, const __half* __restrict__ B1, int K1,
                     const __half* __restrict__ A2, const __half* __restrict__ B2, int K2,
                     const float* __restrict__ Cinit, const float* __restrict__ bias,
                     float* __restrict__ Cout, int Nfull,
                     float* __restrict__ cstate, __half* __restrict__ hout,
                     __half* __restrict__ feats, int t) {
    extern __shared__ char dyn_smem[];
    uint32_t raw  = smem_to_u32(dyn_smem);
    uint32_t base = (raw + 1023u) & ~1023u;

    const int tid  = threadIdx.x;
    const int wid  = tid >> 5;
    const int lane = tid & 31;
    const int lg   = lane >> 2;
    const int lt   = lane & 3;
    const int wm   = wid >> 2;         // 0..1 (M)
    const int wn   = wid & 3;          // 0..3 (N)
    const int row0 = blockIdx.y * 128;
    const int col0 = blockIdx.x * 128;
    const int m0   = wm * 64;
    const int n0   = wn * 32;

    const int lr0 = tid >> 3;          // loader row base
    const int lc  = tid & 7;           // loader 16B column

    float acc[4][4][4];
#pragma unroll
    for (int mi = 0; mi < 4; mi++)
#pragma unroll
        for (int ni = 0; ni < 4; ni++)
#pragma unroll
            for (int r = 0; r < 4; r++) acc[mi][ni][r] = 0.f;

    const int nk = (K1 + K2) / TK_;

    auto load_chunk = [&](int kc, int bsel) {
        const __half* Ag; const __half* Bg; int kk, ldk;
        int k0 = kc * TK_;
        if (k0 < K1) { Ag = A1; Bg = B1; kk = k0;      ldk = K1; }
        else         { Ag = A2; Bg = B2; kk = k0 - K1; ldk = K2; }
        uint32_t sa = base + ((uint32_t)bsel << 14);
        uint32_t sb = base + 32768u + ((uint32_t)bsel << 14);
#pragma unroll
        for (int i = 0; i < 4; i++) {
            int r = lr0 + i * 32;
            cp_async16(sa + SMEM_SWIZZLE_128B(r * 128 + lc * 16),
                       Ag + (size_t)(row0 + r) * ldk + kk + lc * 8);
            cp_async16(sb + SMEM_SWIZZLE_128B(r * 128 + lc * 16),
                       Bg + (size_t)(col0 + r) * ldk + kk + lc * 8);
        }
        CP_COMMIT();
    };

    load_chunk(0, 0);

    for (int k = 0; k < nk; k++) {
        int bsel = k & 1;
        if (k + 1 < nk) { load_chunk(k + 1, bsel ^ 1); CP_WAIT(1); }
        else            { CP_WAIT(0); }
        __syncthreads();

        uint32_t sa = base + ((uint32_t)bsel << 14);
        uint32_t sb = base + 32768u + ((uint32_t)bsel << 14);
        // element (r, k): byte r*128 + (k*2 ^ ((r&7)<<4)); our rows have (r&7)==lg
#pragma unroll
        for (int ks = 0; ks < 4; ks++) {
            uint32_t kb    = (uint32_t)(ks * 32 + lt * 4);
            uint32_t koff  = kb ^ ((uint32_t)lg << 4);
            uint32_t koff8 = (kb + 16u) ^ ((uint32_t)lg << 4);

            uint32_t af[4][4];
#pragma unroll
            for (int mi = 0; mi < 4; mi++) {
                uint32_t rb = sa + (uint32_t)((m0 + mi * 16 + lg) * 128);
                af[mi][0] = lds32(rb + koff);
                af[mi][1] = lds32(rb + 8 * 128 + koff);
                af[mi][2] = lds32(rb + koff8);
                af[mi][3] = lds32(rb + 8 * 128 + koff8);
            }
            uint32_t bf[4][2];
#pragma unroll
            for (int ni = 0; ni < 4; ni++) {
                uint32_t nb = sb + (uint32_t)((n0 + ni * 8 + lg) * 128);
                bf[ni][0] = lds32(nb + koff);
                bf[ni][1] = lds32(nb + koff8);
            }
#pragma unroll
            for (int mi = 0; mi < 4; mi++)
#pragma unroll
                for (int ni = 0; ni < 4; ni++)
                    mma_fp16(acc[mi][ni][0], acc[mi][ni][1],
                             acc[mi][ni][2], acc[mi][ni][3],
                             af[mi][0], af[mi][1], af[mi][2], af[mi][3],
                             bf[ni][0], bf[ni][1]);
        }
        __syncthreads();
    }

    if (MODE == 0) {
        // ---- plain epilogue: fp32 stores ----
#pragma unroll
        for (int mi = 0; mi < 4; mi++) {
            int gr0 = row0 + m0 + mi * 16 + lg;
#pragma unroll
            for (int ni = 0; ni < 4; ni++) {
                int gc = col0 + n0 + ni * 8 + lt * 2;
                float bx = 0.f, by = 0.f;
                if (bias) { bx = bias[gc]; by = bias[gc + 1]; }
                size_t g0 = (size_t)gr0 * Nfull + gc;
                size_t g1 = g0 + (size_t)8 * Nfull;
                float2 v0 = make_float2(acc[mi][ni][0] + bx, acc[mi][ni][1] + by);
                float2 v1 = make_float2(acc[mi][ni][2] + bx, acc[mi][ni][3] + by);
                if (Cinit) {
                    float2 c0v = *(const float2*)(Cinit + g0);
                    float2 c1v = *(const float2*)(Cinit + g1);
                    v0.x += c0v.x; v0.y += c0v.y;
                    v1.x += c1v.x; v1.y += c1v.y;
                }
                *(float2*)(Cout + g0) = v0;
                *(float2*)(Cout + g1) = v1;
            }
        }
    } else {
        // ---- fused LSTM cell epilogue (gate-interleaved columns) ----
        const int p = lt & 1;   // 0: owns (i,f) row lg ; 1: owns (g,o) row lg+8
#pragma unroll
        for (int mi = 0; mi < 4; mi++) {
            int gr0 = row0 + m0 + mi * 16 + lg;
#pragma unroll
            for (int ni = 0; ni < 4; ni++) {
                int gc = col0 + n0 + ni * 8 + lt * 2;
                float v0 = acc[mi][ni][0], v1 = acc[mi][ni][1];
                float v2 = acc[mi][ni][2], v3 = acc[mi][ni][3];
                if (bias) {
                    float bx = bias[gc], by = bias[gc + 1];
                    v0 += bx; v1 += by; v2 += bx; v3 += by;
                }
                if (Cinit) {
                    size_t g0 = (size_t)gr0 * Nfull + gc;
                    size_t g1 = g0 + (size_t)8 * Nfull;
                    float2 c0v = *(const float2*)(Cinit + g0);
                    float2 c1v = *(const float2*)(Cinit + g1);
                    v0 += c0v.x; v1 += c0v.y; v2 += c1v.x; v3 += c1v.y;
                }
                // exchange within (even, odd) lane pair
                float x0 = __shfl_xor_sync(0xffffffffu, v0, 1);
                float x1 = __shfl_xor_sync(0xffffffffu, v1, 1);
                float x2 = __shfl_xor_sync(0xffffffffu, v2, 1);
                float x3 = __shfl_xor_sync(0xffffffffu, v3, 1);
                float gi, gf, gg, go;
                if (p == 0) { gi = v0; gf = v1; gg = x0; go = x1; }  // row lg
                else        { gi = x2; gf = x3; gg = v2; go = v3; }  // row lg+8
                int row = gr0 + p * 8;
                int h   = gc >> 2;
                int ci  = row * D_ + h;
                float c_old = cstate[ci];
                float cn = sigmoidf_(gf) * c_old + sigmoidf_(gi) * tanhf(gg);
                float hn = sigmoidf_(go) * tanhf(cn);
                cstate[ci] = cn;
                __half hh = __float2half_rn(hn);
                hout[ci] = hh;
                if (feats) feats[((size_t)row * BAR_ + t) * D_ + h] = hh;
            }
        }
    }
}

// ---------------------------------------------------------------------------
// Launch
// ---------------------------------------------------------------------------
extern "C" void kernel_launch(void* const* d_in, const int* in_sizes, int n_in,
                              void* d_out, int out_size) {
    const float* z       = (const float*)d_in[0];
    const float* gamma   = (const float*)d_in[1];
    const float* beta    = (const float*)d_in[2];
    const float* W_ih0   = (const float*)d_in[3];
    const float* W_hh0   = (const float*)d_in[4];
    const float* b_ih0   = (const float*)d_in[5];
    const float* b_hh0   = (const float*)d_in[6];
    const float* W_ih1   = (const float*)d_in[7];
    const float* W_hh1   = (const float*)d_in[8];
    const float* b_ih1   = (const float*)d_in[9];
    const float* b_hh1   = (const float*)d_in[10];
    const float* W_lin   = (const float*)d_in[11];
    const float* b_lin   = (const float*)d_in[12];
    float* out = (float*)d_out;

    __half *znh, *h0a, *h0b, *h1a, *h1b, *featsh;
    __half *wih0, *whh0, *wih1, *whh1, *wlin;
    float *c0, *c1, *x0p, *b0i, *b1i;
    cudaGetSymbolAddress((void**)&znh,   g_znh);
    cudaGetSymbolAddress((void**)&h0a,   g_h0a);
    cudaGetSymbolAddress((void**)&h0b,   g_h0b);
    cudaGetSymbolAddress((void**)&h1a,   g_h1a);
    cudaGetSymbolAddress((void**)&h1b,   g_h1b);
    cudaGetSymbolAddress((void**)&c0,    g_c0);
    cudaGetSymbolAddress((void**)&c1,    g_c1);
    cudaGetSymbolAddress((void**)&x0p,   g_x0p);
    cudaGetSymbolAddress((void**)&featsh,g_feats);
    cudaGetSymbolAddress((void**)&b0i,   g_b0i);
    cudaGetSymbolAddress((void**)&b1i,   g_b1i);
    cudaGetSymbolAddress((void**)&wih0,  g_wih0);
    cudaGetSymbolAddress((void**)&whh0,  g_whh0);
    cudaGetSymbolAddress((void**)&wih1,  g_wih1);
    cudaGetSymbolAddress((void**)&whh1,  g_whh1);
    cudaGetSymbolAddress((void**)&wlin,  g_wlin);

    cudaFuncSetAttribute(gemm_mma_kernel<0>,
                         cudaFuncAttributeMaxDynamicSharedMemorySize, DYN_BYTES);
    cudaFuncSetAttribute(gemm_mma_kernel<1>,
                         cudaFuncAttributeMaxDynamicSharedMemorySize, DYN_BYTES);

    // 1. BN + inits + interleaved bias/weight prep
    bn_stats_kernel<<<D_ / 32, dim3(32, 8)>>>(z, gamma, beta);
    bn_apply_init_kernel<<<(B_ * D_) / 512, 512>>>(z);
    bias_interleave_kernel<<<H4 / 256, 256>>>(b_ih0, b_hh0, b_ih1, b_hh1);
    weight_interleave_kernel<<<(H4 * 256) / 256, 256>>>(W_ih0, wih0);
    weight_interleave_kernel<<<(H4 * 256) / 256, 256>>>(W_hh0, whh0);
    weight_interleave_kernel<<<(H4 * 256) / 256, 256>>>(W_ih1, wih1);
    weight_interleave_kernel<<<(H4 * 256) / 256, 256>>>(W_hh1, whh1);
    weight_fp16_kernel<<<(D_ * D_ / 4) / 256, 256>>>(W_lin, wlin, D_ * D_ / 4);

    dim3 grid_layer(H4 / 128, B_ / 128);        // (32, 8) = 256 CTAs

    // 2. x0_proj (interleaved cols) = zn @ wih0^T + b0i
    gemm_mma_kernel<0><<<grid_layer, 256, DYN_BYTES>>>(
        znh, wih0, D_, nullptr, nullptr, 0, nullptr, b0i, x0p, H4,
        nullptr, nullptr, nullptr, 0);

    // 3. 32 recurrent steps, 2 fused launches each; h buffers ping-pong so
    //    a launch never writes the buffer its own mainloop (or a sibling CTA)
    //    is still reading.
    __half* h0cur = h0a; __half* h0nxt = h0b;
    __half* h1cur = h1a; __half* h1nxt = h1b;
    for (int t = 0; t < BAR_; t++) {
        gemm_mma_kernel<1><<<grid_layer, 256, DYN_BYTES>>>(
            h0cur, whh0, D_, nullptr, nullptr, 0, x0p, nullptr, nullptr, H4,
            c0, h0nxt, nullptr, 0);
        gemm_mma_kernel<1><<<grid_layer, 256, DYN_BYTES>>>(
            h0nxt, wih1, D_, h1cur, whh1, D_, nullptr, b1i, nullptr, H4,
            c1, h1nxt, featsh, t);
        __half* tmp;
        tmp = h0cur; h0cur = h0nxt; h0nxt = tmp;
        tmp = h1cur; h1cur = h1nxt; h1nxt = tmp;
    }

    // 4. out = feats(B*32, H) @ W_lin^T + b_lin
    dim3 grid_head(D_ / 128, (B_ * BAR_) / 128);   // (8, 256)
    gemm_mma_kernel<0><<<grid_head, 256, DYN_BYTES>>>(
        featsh, wlin, D_, nullptr, nullptr, 0, nullptr, b_lin, out, D_,
        nullptr, nullptr, nullptr, 0);
}